// round 2
// baseline (speedup 1.0000x reference)
#include <cuda_runtime.h>
#include <cuda_bf16.h>

typedef unsigned long long ull;

// ---------------- problem constants ----------------
#define NN 100000
#define EE 3200000

// ---------------- scratch (device globals; no allocations allowed) ----------------
__device__ int   g_cnt[NN];
__device__ int   g_rowptr[NN + 1];
__device__ int   g_woff[NN];
__device__ int   g_scol[EE];
__device__ float g_sval[EE];
__device__ float g_Y[(size_t)NN * 768];   // [u0 | u1 | p]  (layer-1 GEMM out)
__device__ float g_S[(size_t)NN * 256];   // s = u1 + 2 L p
__device__ float g_H[(size_t)NN * 256];   // h (relu)
__device__ float g_Z[(size_t)NN * 192];   // [v0 | v1 | p2] (layer-2 GEMM out)
__device__ float g_S2[(size_t)NN * 64];   // s2
__device__ float g_Acat[256 * 768];       // [A0-A2 | A1 | A2], row f, col j
__device__ float g_Bcat[256 * 192];       // [B0-B2 | B1 | B2], row h, col c

// ---------------- small helpers ----------------
__device__ __forceinline__ ull ffma2(ull a, ull b, ull c) {
    ull d;
    asm("fma.rn.f32x2 %0, %1, %2, %3;" : "=l"(d) : "l"(a), "l"(b), "l"(c));
    return d;
}
__device__ __forceinline__ ull dupf(float x) {
    ull d; asm("mov.b64 %0, {%1, %1};" : "=l"(d) : "f"(x)); return d;
}
__device__ __forceinline__ ull packf2(float lo, float hi) {
    ull d; asm("mov.b64 %0, {%1, %2};" : "=l"(d) : "f"(lo), "f"(hi)); return d;
}
__device__ __forceinline__ float2 unpk(ull v) {
    float2 r; asm("mov.b64 {%0, %1}, %2;" : "=f"(r.x), "=f"(r.y) : "l"(v)); return r;
}

// ---------------- CSR build ----------------
__global__ __launch_bounds__(256) void zero_i(int* p, int n) {
    int i = blockIdx.x * 256 + threadIdx.x;
    if (i < n) p[i] = 0;
}

__global__ __launch_bounds__(256) void hist_k(const int* __restrict__ rows, int* cnt, int E) {
    int e = blockIdx.x * 256 + threadIdx.x;
    if (e < E) atomicAdd(&cnt[__ldg(rows + e)], 1);
}

__global__ __launch_bounds__(1024) void scan_k(const int* __restrict__ cnt, int* rowptr, int* woff, int N, int E) {
    __shared__ int partial[1024];
    int t = threadIdx.x;
    int CH = (N + 1023) >> 10;
    int start = t * CH;
    int s = 0;
    for (int i = 0; i < CH; i++) {
        int idx = start + i;
        if (idx < N) s += cnt[idx];
    }
    partial[t] = s;
    __syncthreads();
    // Hillis-Steele inclusive scan
    for (int off = 1; off < 1024; off <<= 1) {
        int v = (t >= off) ? partial[t - off] : 0;
        __syncthreads();
        partial[t] += v;
        __syncthreads();
    }
    int run = partial[t] - s;  // exclusive base
    for (int i = 0; i < CH; i++) {
        int idx = start + i;
        if (idx < N) {
            rowptr[idx] = run;
            woff[idx] = run;
            run += cnt[idx];
        }
    }
    if (t == 0) rowptr[N] = E;
}

__global__ __launch_bounds__(256) void scatter_k(const int* __restrict__ rows, const int* __restrict__ cols,
                                                 const float* __restrict__ vals,
                                                 int* woff, int* scol, float* sval, int E) {
    int e = blockIdx.x * 256 + threadIdx.x;
    if (e < E) {
        int r = __ldg(rows + e);
        int p = atomicAdd(&woff[r], 1);
        scol[p] = __ldg(cols + e);
        sval[p] = __ldg(vals + e);
    }
}

// ---------------- weight re-layout ----------------
// A_k[f,h] = W1[h, 3f+k] ; Acat[f, 0:256)=A0-A2, [256:512)=A1, [512:768)=A2
// B_k[j,o] = W2[o, 3j+k] ; Bcat[j, 0:64)=B0-B2, [64:128)=B1, [128:192)=B2
__global__ __launch_bounds__(256) void prep_w(const float* __restrict__ W1, const float* __restrict__ W2,
                                              float* Acat, float* Bcat) {
    int i = blockIdx.x * 256 + threadIdx.x;
    if (i < 256 * 768) {
        int f = i / 768, j = i % 768;
        float v;
        if (j < 256)       v = W1[j * 768 + 3 * f] - W1[j * 768 + 3 * f + 2];
        else if (j < 512)  v = W1[(j - 256) * 768 + 3 * f + 1];
        else               v = W1[(j - 512) * 768 + 3 * f + 2];
        Acat[i] = v;
    } else {
        int i2 = i - 256 * 768;
        if (i2 < 256 * 192) {
            int j = i2 / 192, c = i2 % 192;
            float v;
            if (c < 64)        v = W2[c * 768 + 3 * j] - W2[c * 768 + 3 * j + 2];
            else if (c < 128)  v = W2[(c - 64) * 768 + 3 * j + 1];
            else               v = W2[(c - 128) * 768 + 3 * j + 2];
            Bcat[i2] = v;
        }
    }
}

// ---------------- fp32 SGEMM with f32x2 FMAs ----------------
// C[M,NC] = X[M,256] @ W[256,NC].  BM=128, BK=16, 256 threads.
// BN=128 -> TN=8 (thread tile 8x8);  BN=64 -> TN=4 (8x4).
template <int BN, int TN>
__global__ __launch_bounds__(256) void sgemm(const float* __restrict__ X, const float* __restrict__ W,
                                             float* __restrict__ C, int M, int NC) {
    __shared__ float As[16][132];
    __shared__ float Bs[16][BN];
    int m0 = blockIdx.x * 128;
    int n0 = blockIdx.y * BN;
    int tid = threadIdx.x;
    int ty = tid >> 4, tx = tid & 15;

    ull acc[8][TN / 2];
#pragma unroll
    for (int i = 0; i < 8; i++)
#pragma unroll
        for (int j = 0; j < TN / 2; j++) acc[i][j] = 0ull;

    for (int k0 = 0; k0 < 256; k0 += 16) {
        // load A tile (transposed into As[kk][m])
#pragma unroll
        for (int p = 0; p < 2; p++) {
            int mm = (tid >> 2) + p * 64;
            int ks = (tid & 3) * 4;
            float4 v = make_float4(0.f, 0.f, 0.f, 0.f);
            int r = m0 + mm;
            if (r < M) v = *(const float4*)(X + (size_t)r * 256 + k0 + ks);
            As[ks + 0][mm] = v.x;
            As[ks + 1][mm] = v.y;
            As[ks + 2][mm] = v.z;
            As[ks + 3][mm] = v.w;
        }
        // load B tile
        if (BN == 128) {
#pragma unroll
            for (int p = 0; p < 2; p++) {
                int kk = (tid >> 5) + p * 8;
                int n4 = tid & 31;
                *(float4*)&Bs[kk][n4 * 4] = *(const float4*)(W + (size_t)(k0 + kk) * NC + n0 + n4 * 4);
            }
        } else {
            int kk = tid >> 4;
            int n4 = tid & 15;
            *(float4*)&Bs[kk][n4 * 4] = *(const float4*)(W + (size_t)(k0 + kk) * NC + n0 + n4 * 4);
        }
        __syncthreads();

#pragma unroll
        for (int kk = 0; kk < 16; kk++) {
            float a[8];
            *(float4*)&a[0] = *(const float4*)&As[kk][ty * 8];
            *(float4*)&a[4] = *(const float4*)&As[kk][ty * 8 + 4];
            ull bp[TN / 2];
#pragma unroll
            for (int j = 0; j < TN / 2; j++) {
                float2 b2 = *(const float2*)&Bs[kk][tx * TN + j * 2];
                bp[j] = packf2(b2.x, b2.y);
            }
#pragma unroll
            for (int i = 0; i < 8; i++) {
                ull ap = dupf(a[i]);
#pragma unroll
                for (int j = 0; j < TN / 2; j++) acc[i][j] = ffma2(ap, bp[j], acc[i][j]);
            }
        }
        __syncthreads();
    }

#pragma unroll
    for (int i = 0; i < 8; i++) {
        int r = m0 + ty * 8 + i;
        if (r >= M) continue;
        float outv[TN];
#pragma unroll
        for (int j = 0; j < TN / 2; j++) {
            float2 u = unpk(acc[i][j]);
            outv[2 * j] = u.x;
            outv[2 * j + 1] = u.y;
        }
#pragma unroll
        for (int j4 = 0; j4 < TN / 4; j4++)
            *(float4*)(C + (size_t)r * NC + n0 + tx * TN + j4 * 4) = *(float4*)&outv[j4 * 4];
    }
}

// ---------------- CSR gather SpMM with fused epilogue ----------------
// out[row] = addv[row] + scale * (L @ src)[row] (+ bias) (relu optional)
// LPR = float4 lanes per row (64 for width 256, 16 for width 64). 256 threads/block.
template <int LPR, bool RELU, bool HASBIAS>
__global__ __launch_bounds__(256) void spmm_k(const int* __restrict__ rowptr, const int* __restrict__ scol,
                                              const float* __restrict__ sval,
                                              const float4* __restrict__ src, int ss,
                                              const float4* __restrict__ addv, int as_,
                                              float4* __restrict__ out, int os,
                                              const float* __restrict__ bias, float scale, int N) {
    int tid = threadIdx.x;
    int lane = tid & (LPR - 1);
    int row = blockIdx.x * (256 / LPR) + tid / LPR;
    if (row >= N) return;

    int e0 = __ldg(rowptr + row);
    int e1 = __ldg(rowptr + row + 1);

    float4 acc = make_float4(0.f, 0.f, 0.f, 0.f);
    float4 acc2 = make_float4(0.f, 0.f, 0.f, 0.f);
    int e = e0;
    // 8-wide: two independent accumulators, 8 outstanding gathers (MLP)
    for (; e + 8 <= e1; e += 8) {
        int   c0 = __ldg(scol + e),     c1 = __ldg(scol + e + 1),
              c2 = __ldg(scol + e + 2), c3 = __ldg(scol + e + 3),
              c4 = __ldg(scol + e + 4), c5 = __ldg(scol + e + 5),
              c6 = __ldg(scol + e + 6), c7 = __ldg(scol + e + 7);
        float v0 = __ldg(sval + e),     v1 = __ldg(sval + e + 1),
              v2 = __ldg(sval + e + 2), v3 = __ldg(sval + e + 3),
              v4 = __ldg(sval + e + 4), v5 = __ldg(sval + e + 5),
              v6 = __ldg(sval + e + 6), v7 = __ldg(sval + e + 7);
        float4 x0 = __ldg(src + c0 * ss + lane);
        float4 x1 = __ldg(src + c1 * ss + lane);
        float4 x2 = __ldg(src + c2 * ss + lane);
        float4 x3 = __ldg(src + c3 * ss + lane);
        float4 x4 = __ldg(src + c4 * ss + lane);
        float4 x5 = __ldg(src + c5 * ss + lane);
        float4 x6 = __ldg(src + c6 * ss + lane);
        float4 x7 = __ldg(src + c7 * ss + lane);
        acc.x  += v0 * x0.x; acc.y  += v0 * x0.y; acc.z  += v0 * x0.z; acc.w  += v0 * x0.w;
        acc2.x += v1 * x1.x; acc2.y += v1 * x1.y; acc2.z += v1 * x1.z; acc2.w += v1 * x1.w;
        acc.x  += v2 * x2.x; acc.y  += v2 * x2.y; acc.z  += v2 * x2.z; acc.w  += v2 * x2.w;
        acc2.x += v3 * x3.x; acc2.y += v3 * x3.y; acc2.z += v3 * x3.z; acc2.w += v3 * x3.w;
        acc.x  += v4 * x4.x; acc.y  += v4 * x4.y; acc.z  += v4 * x4.z; acc.w  += v4 * x4.w;
        acc2.x += v5 * x5.x; acc2.y += v5 * x5.y; acc2.z += v5 * x5.z; acc2.w += v5 * x5.w;
        acc.x  += v6 * x6.x; acc.y  += v6 * x6.y; acc.z  += v6 * x6.z; acc.w  += v6 * x6.w;
        acc2.x += v7 * x7.x; acc2.y += v7 * x7.y; acc2.z += v7 * x7.z; acc2.w += v7 * x7.w;
    }
    for (; e < e1; e++) {
        int c = __ldg(scol + e);
        float v = __ldg(sval + e);
        float4 xg = __ldg(src + c * ss + lane);
        acc.x += v * xg.x; acc.y += v * xg.y; acc.z += v * xg.z; acc.w += v * xg.w;
    }
    acc.x += acc2.x; acc.y += acc2.y; acc.z += acc2.z; acc.w += acc2.w;

    float4 r = addv[row * as_ + lane];
    r.x += scale * acc.x; r.y += scale * acc.y; r.z += scale * acc.z; r.w += scale * acc.w;
    if (HASBIAS) {
        float4 b = ((const float4*)bias)[lane];
        r.x += b.x; r.y += b.y; r.z += b.z; r.w += b.w;
    }
    if (RELU) {
        r.x = fmaxf(r.x, 0.f); r.y = fmaxf(r.y, 0.f); r.z = fmaxf(r.z, 0.f); r.w = fmaxf(r.w, 0.f);
    }
    out[row * os + lane] = r;
}

// ---------------- launch ----------------
extern "C" void kernel_launch(void* const* d_in, const int* in_sizes, int n_in,
                              void* d_out, int out_size) {
    const float* x    = (const float*)d_in[0];
    const int*   rows = (const int*)d_in[1];
    const int*   cols = (const int*)d_in[2];
    const float* vals = (const float*)d_in[3];
    const float* W1   = (const float*)d_in[4];
    const float* b1   = (const float*)d_in[5];
    const float* W2   = (const float*)d_in[6];
    const float* b2   = (const float*)d_in[7];
    float* outp = (float*)d_out;

    const int N = NN;
    const int E = in_sizes[1];

    int *cnt, *rowptr, *woff, *scol;
    float *sval, *Y, *S, *H, *Z, *S2, *Acat, *Bcat;
    cudaGetSymbolAddress((void**)&cnt, g_cnt);
    cudaGetSymbolAddress((void**)&rowptr, g_rowptr);
    cudaGetSymbolAddress((void**)&woff, g_woff);
    cudaGetSymbolAddress((void**)&scol, g_scol);
    cudaGetSymbolAddress((void**)&sval, g_sval);
    cudaGetSymbolAddress((void**)&Y, g_Y);
    cudaGetSymbolAddress((void**)&S, g_S);
    cudaGetSymbolAddress((void**)&H, g_H);
    cudaGetSymbolAddress((void**)&Z, g_Z);
    cudaGetSymbolAddress((void**)&S2, g_S2);
    cudaGetSymbolAddress((void**)&Acat, g_Acat);
    cudaGetSymbolAddress((void**)&Bcat, g_Bcat);

    // CSR build (deterministic work per launch)
    zero_i<<<(N + 255) / 256, 256>>>(cnt, N);
    hist_k<<<(E + 255) / 256, 256>>>(rows, cnt, E);
    scan_k<<<1, 1024>>>(cnt, rowptr, woff, N, E);
    scatter_k<<<(E + 255) / 256, 256>>>(rows, cols, vals, woff, scol, sval, E);

    // weight re-layout
    prep_w<<<(256 * 768 + 256 * 192 + 255) / 256, 256>>>(W1, W2, Acat, Bcat);

    int mtiles = (N + 127) / 128;

    // Layer 1: Y = x @ [A0-A2 | A1 | A2]  ->  u0 | u1 | p
    sgemm<128, 8><<<dim3(mtiles, 6), 256>>>(x, Acat, Y, N, 768);
    // s = u1 + 2 * L p
    spmm_k<64, false, false><<<(N + 3) / 4, 256>>>(rowptr, scol, sval,
        (const float4*)Y + 128, 192, (const float4*)Y + 64, 192,
        (float4*)S, 64, nullptr, 2.0f, N);
    // h = relu(u0 + L s + b1)
    spmm_k<64, true, true><<<(N + 3) / 4, 256>>>(rowptr, scol, sval,
        (const float4*)S, 64, (const float4*)Y, 192,
        (float4*)H, 64, b1, 1.0f, N);

    // Layer 2: Z = h @ [B0-B2 | B1 | B2]  ->  v0 | v1 | p2
    sgemm<64, 4><<<dim3(mtiles, 3), 256>>>(H, Bcat, Z, N, 192);
    // s2 = v1 + 2 * L p2
    spmm_k<16, false, false><<<(N + 15) / 16, 256>>>(rowptr, scol, sval,
        (const float4*)Z + 32, 48, (const float4*)Z + 16, 48,
        (float4*)S2, 16, nullptr, 2.0f, N);
    // out = v0 + L s2 + b2
    spmm_k<16, false, true><<<(N + 15) / 16, 256>>>(rowptr, scol, sval,
        (const float4*)S2, 16, (const float4*)Z, 48,
        (float4*)outp, 16, b2, 1.0f, N);
}

// round 3
// speedup vs baseline: 1.0407x; 1.0407x over previous
#include <cuda_runtime.h>
#include <cuda_bf16.h>

typedef unsigned long long ull;

// ---------------- problem constants ----------------
#define NN 100000
#define EE 3200000

// ---------------- scratch (device globals; no allocations allowed) ----------------
__device__ int   g_cnt[NN];
__device__ int   g_rowptr[NN + 1];
__device__ int   g_woff[NN];
__device__ int   g_scol[EE];
__device__ float g_sval[EE];
__device__ float g_Y[(size_t)NN * 768];   // [u0 | u1 | p]  (layer-1 GEMM out)
__device__ float g_S[(size_t)NN * 256];   // s = u1 + 2 L p
__device__ float g_H[(size_t)NN * 256];   // h (relu)
__device__ float g_Z[(size_t)NN * 192];   // [v0 | v1 | p2] (layer-2 GEMM out)
__device__ float g_S2[(size_t)NN * 64];   // s2
__device__ float g_Acat[256 * 768];       // [A0-A2 | A1 | A2], row f, col j
__device__ float g_Bcat[256 * 192];       // [B0-B2 | B1 | B2], row h, col c

// ---------------- small helpers ----------------
__device__ __forceinline__ ull ffma2(ull a, ull b, ull c) {
    ull d;
    asm("fma.rn.f32x2 %0, %1, %2, %3;" : "=l"(d) : "l"(a), "l"(b), "l"(c));
    return d;
}
__device__ __forceinline__ ull dupf(float x) {
    ull d; asm("mov.b64 %0, {%1, %1};" : "=l"(d) : "f"(x)); return d;
}
__device__ __forceinline__ float2 unpk(ull v) {
    float2 r; asm("mov.b64 {%0, %1}, %2;" : "=f"(r.x), "=f"(r.y) : "l"(v)); return r;
}

// ---------------- CSR build ----------------
__global__ __launch_bounds__(256) void zero_i(int* p, int n) {
    int i = blockIdx.x * 256 + threadIdx.x;
    if (i < n) p[i] = 0;
}

__global__ __launch_bounds__(256) void hist_k(const int* __restrict__ rows, int* cnt, int E) {
    int e = blockIdx.x * 256 + threadIdx.x;
    if (e < E) atomicAdd(&cnt[__ldg(rows + e)], 1);
}

__global__ __launch_bounds__(1024) void scan_k(const int* __restrict__ cnt, int* rowptr, int* woff, int N, int E) {
    __shared__ int partial[1024];
    int t = threadIdx.x;
    int CH = (N + 1023) >> 10;
    int start = t * CH;
    int s = 0;
    for (int i = 0; i < CH; i++) {
        int idx = start + i;
        if (idx < N) s += cnt[idx];
    }
    partial[t] = s;
    __syncthreads();
    for (int off = 1; off < 1024; off <<= 1) {
        int v = (t >= off) ? partial[t - off] : 0;
        __syncthreads();
        partial[t] += v;
        __syncthreads();
    }
    int run = partial[t] - s;  // exclusive base
    for (int i = 0; i < CH; i++) {
        int idx = start + i;
        if (idx < N) {
            rowptr[idx] = run;
            woff[idx] = run;
            run += cnt[idx];
        }
    }
    if (t == 0) rowptr[N] = E;
}

__global__ __launch_bounds__(256) void scatter_k(const int* __restrict__ rows, const int* __restrict__ cols,
                                                 const float* __restrict__ vals,
                                                 int* woff, int* scol, float* sval, int E) {
    int e = blockIdx.x * 256 + threadIdx.x;
    if (e < E) {
        int r = __ldg(rows + e);
        int p = atomicAdd(&woff[r], 1);
        scol[p] = __ldg(cols + e);
        sval[p] = __ldg(vals + e);
    }
}

// ---------------- weight re-layout ----------------
__global__ __launch_bounds__(256) void prep_w(const float* __restrict__ W1, const float* __restrict__ W2,
                                              float* Acat, float* Bcat) {
    int i = blockIdx.x * 256 + threadIdx.x;
    if (i < 256 * 768) {
        int f = i / 768, j = i % 768;
        float v;
        if (j < 256)       v = W1[j * 768 + 3 * f] - W1[j * 768 + 3 * f + 2];
        else if (j < 512)  v = W1[(j - 256) * 768 + 3 * f + 1];
        else               v = W1[(j - 512) * 768 + 3 * f + 2];
        Acat[i] = v;
    } else {
        int i2 = i - 256 * 768;
        if (i2 < 256 * 192) {
            int j = i2 / 192, c = i2 % 192;
            float v;
            if (c < 64)        v = W2[c * 768 + 3 * j] - W2[c * 768 + 3 * j + 2];
            else if (c < 128)  v = W2[(c - 64) * 768 + 3 * j + 1];
            else               v = W2[(c - 128) * 768 + 3 * j + 2];
            Bcat[i2] = v;
        }
    }
}

// ---------------- pipelined fp32 SGEMM with f32x2 FMAs ----------------
// C[M,NC] = X[M,256] @ W[256,NC].  BM=128, BK=16, 256 threads, double-buffered.
// BN=128 -> TN=8 (8x8 per thread); BN=64 -> TN=4 (8x4).
template <int BN, int TN>
__global__ __launch_bounds__(256, 2) void sgemm(const float* __restrict__ X, const float* __restrict__ W,
                                                float* __restrict__ C, int M, int NC) {
    __shared__ float As[2][16][132];
    __shared__ float Bs[2][16][BN];
    int m0 = blockIdx.x * 128;
    int n0 = blockIdx.y * BN;
    int tid = threadIdx.x;
    int ty = tid >> 4, tx = tid & 15;

    // A-load mapping: thread loads 2 float4s (rows mmA+{0,64}, cols ksA..ksA+3)
    int mmA = tid >> 2;
    int ksA = (tid & 3) * 4;
    // B-load mapping
    int kkB = (BN == 128) ? (tid >> 5) : (tid >> 4);
    int nB  = (BN == 128) ? ((tid & 31) * 4) : ((tid & 15) * 4);

    ull acc[8][TN / 2];
#pragma unroll
    for (int i = 0; i < 8; i++)
#pragma unroll
        for (int j = 0; j < TN / 2; j++) acc[i][j] = 0ull;

    float4 av[2], bv[2];

    // ---- register loads for tile at k0 ----
    auto load_tile = [&](int k0) {
#pragma unroll
        for (int p = 0; p < 2; p++) {
            int r = m0 + mmA + p * 64;
            av[p] = (r < M) ? *(const float4*)(X + (size_t)r * 256 + k0 + ksA)
                            : make_float4(0.f, 0.f, 0.f, 0.f);
        }
        if (BN == 128) {
#pragma unroll
            for (int p = 0; p < 2; p++)
                bv[p] = *(const float4*)(W + (size_t)(k0 + kkB + p * 8) * NC + n0 + nB);
        } else {
            bv[0] = *(const float4*)(W + (size_t)(k0 + kkB) * NC + n0 + nB);
        }
    };

    // ---- store regs -> smem stage ----
    auto store_tile = [&](int buf) {
#pragma unroll
        for (int p = 0; p < 2; p++) {
            As[buf][ksA + 0][mmA + p * 64] = av[p].x;
            As[buf][ksA + 1][mmA + p * 64] = av[p].y;
            As[buf][ksA + 2][mmA + p * 64] = av[p].z;
            As[buf][ksA + 3][mmA + p * 64] = av[p].w;
        }
        if (BN == 128) {
#pragma unroll
            for (int p = 0; p < 2; p++)
                *(float4*)&Bs[buf][kkB + p * 8][nB] = bv[p];
        } else {
            *(float4*)&Bs[buf][kkB][nB] = bv[0];
        }
    };

    // ---- compute one 16-deep K stage from smem buffer ----
    auto compute = [&](int buf) {
#pragma unroll
        for (int kk = 0; kk < 16; kk++) {
            float a[8];
            *(float4*)&a[0] = *(const float4*)&As[buf][kk][ty * 8];
            *(float4*)&a[4] = *(const float4*)&As[buf][kk][ty * 8 + 4];
            ull bp[TN / 2];
#pragma unroll
            for (int j4 = 0; j4 < TN / 4; j4++) {
                float4 b4 = *(const float4*)&Bs[buf][kk][tx * TN + j4 * 4];
                ull lo; asm("mov.b64 %0, {%1, %2};" : "=l"(lo) : "f"(b4.x), "f"(b4.y));
                ull hi; asm("mov.b64 %0, {%1, %2};" : "=l"(hi) : "f"(b4.z), "f"(b4.w));
                bp[j4 * 2] = lo;
                bp[j4 * 2 + 1] = hi;
            }
#pragma unroll
            for (int i = 0; i < 8; i++) {
                ull ap = dupf(a[i]);
#pragma unroll
                for (int j = 0; j < TN / 2; j++) acc[i][j] = ffma2(ap, bp[j], acc[i][j]);
            }
        }
    };

    const int NIT = 256 / 16;
    load_tile(0);
    store_tile(0);
    __syncthreads();

    for (int it = 0; it < NIT - 1; it++) {
        load_tile((it + 1) * 16);     // prefetch next tile into regs (LDG in flight)
        compute(it & 1);              // compute current stage
        store_tile((it + 1) & 1);     // drain regs into other buffer
        __syncthreads();
    }
    compute((NIT - 1) & 1);

    // ---- epilogue ----
#pragma unroll
    for (int i = 0; i < 8; i++) {
        int r = m0 + ty * 8 + i;
        if (r >= M) continue;
        float outv[TN];
#pragma unroll
        for (int j = 0; j < TN / 2; j++) {
            float2 u = unpk(acc[i][j]);
            outv[2 * j] = u.x;
            outv[2 * j + 1] = u.y;
        }
#pragma unroll
        for (int j4 = 0; j4 < TN / 4; j4++)
            *(float4*)(C + (size_t)r * NC + n0 + tx * TN + j4 * 4) = *(float4*)&outv[j4 * 4];
    }
}

// ---------------- CSR gather SpMM with fused epilogue ----------------
// out[row] = addv[row] + scale * (L @ src)[row] (+ bias) (relu optional)
// addv read with evict-first (__ldcs), out written streaming (__stcs) so the
// gather working set (src) keeps L2 residency.
template <int LPR, bool RELU, bool HASBIAS>
__global__ __launch_bounds__(256) void spmm_k(const int* __restrict__ rowptr, const int* __restrict__ scol,
                                              const float* __restrict__ sval,
                                              const float4* __restrict__ src, int ss,
                                              const float4* __restrict__ addv, int as_,
                                              float4* __restrict__ out, int os,
                                              const float* __restrict__ bias, float scale, int N) {
    int tid = threadIdx.x;
    int lane = tid & (LPR - 1);
    int row = blockIdx.x * (256 / LPR) + tid / LPR;
    if (row >= N) return;

    int e0 = __ldg(rowptr + row);
    int e1 = __ldg(rowptr + row + 1);

    float4 acc = make_float4(0.f, 0.f, 0.f, 0.f);
    float4 acc2 = make_float4(0.f, 0.f, 0.f, 0.f);
    int e = e0;
    for (; e + 8 <= e1; e += 8) {
        int   c0 = __ldg(scol + e),     c1 = __ldg(scol + e + 1),
              c2 = __ldg(scol + e + 2), c3 = __ldg(scol + e + 3),
              c4 = __ldg(scol + e + 4), c5 = __ldg(scol + e + 5),
              c6 = __ldg(scol + e + 6), c7 = __ldg(scol + e + 7);
        float v0 = __ldg(sval + e),     v1 = __ldg(sval + e + 1),
              v2 = __ldg(sval + e + 2), v3 = __ldg(sval + e + 3),
              v4 = __ldg(sval + e + 4), v5 = __ldg(sval + e + 5),
              v6 = __ldg(sval + e + 6), v7 = __ldg(sval + e + 7);
        float4 x0 = __ldg(src + c0 * ss + lane);
        float4 x1 = __ldg(src + c1 * ss + lane);
        float4 x2 = __ldg(src + c2 * ss + lane);
        float4 x3 = __ldg(src + c3 * ss + lane);
        float4 x4 = __ldg(src + c4 * ss + lane);
        float4 x5 = __ldg(src + c5 * ss + lane);
        float4 x6 = __ldg(src + c6 * ss + lane);
        float4 x7 = __ldg(src + c7 * ss + lane);
        acc.x  += v0 * x0.x; acc.y  += v0 * x0.y; acc.z  += v0 * x0.z; acc.w  += v0 * x0.w;
        acc2.x += v1 * x1.x; acc2.y += v1 * x1.y; acc2.z += v1 * x1.z; acc2.w += v1 * x1.w;
        acc.x  += v2 * x2.x; acc.y  += v2 * x2.y; acc.z  += v2 * x2.z; acc.w  += v2 * x2.w;
        acc2.x += v3 * x3.x; acc2.y += v3 * x3.y; acc2.z += v3 * x3.z; acc2.w += v3 * x3.w;
        acc.x  += v4 * x4.x; acc.y  += v4 * x4.y; acc.z  += v4 * x4.z; acc.w  += v4 * x4.w;
        acc2.x += v5 * x5.x; acc2.y += v5 * x5.y; acc2.z += v5 * x5.z; acc2.w += v5 * x5.w;
        acc.x  += v6 * x6.x; acc.y  += v6 * x6.y; acc.z  += v6 * x6.z; acc.w  += v6 * x6.w;
        acc2.x += v7 * x7.x; acc2.y += v7 * x7.y; acc2.z += v7 * x7.z; acc2.w += v7 * x7.w;
    }
    for (; e < e1; e++) {
        int c = __ldg(scol + e);
        float v = __ldg(sval + e);
        float4 xg = __ldg(src + c * ss + lane);
        acc.x += v * xg.x; acc.y += v * xg.y; acc.z += v * xg.z; acc.w += v * xg.w;
    }
    acc.x += acc2.x; acc.y += acc2.y; acc.z += acc2.z; acc.w += acc2.w;

    float4 r = __ldcs(addv + row * as_ + lane);   // streaming: don't pollute L2
    r.x += scale * acc.x; r.y += scale * acc.y; r.z += scale * acc.z; r.w += scale * acc.w;
    if (HASBIAS) {
        float4 b = ((const float4*)bias)[lane];
        r.x += b.x; r.y += b.y; r.z += b.z; r.w += b.w;
    }
    if (RELU) {
        r.x = fmaxf(r.x, 0.f); r.y = fmaxf(r.y, 0.f); r.z = fmaxf(r.z, 0.f); r.w = fmaxf(r.w, 0.f);
    }
    __stcs(out + row * os + lane, r);             // streaming write
}

// ---------------- launch ----------------
extern "C" void kernel_launch(void* const* d_in, const int* in_sizes, int n_in,
                              void* d_out, int out_size) {
    const float* x    = (const float*)d_in[0];
    const int*   rows = (const int*)d_in[1];
    const int*   cols = (const int*)d_in[2];
    const float* vals = (const float*)d_in[3];
    const float* W1   = (const float*)d_in[4];
    const float* b1   = (const float*)d_in[5];
    const float* W2   = (const float*)d_in[6];
    const float* b2   = (const float*)d_in[7];
    float* outp = (float*)d_out;

    const int N = NN;
    const int E = in_sizes[1];

    int *cnt, *rowptr, *woff, *scol;
    float *sval, *Y, *S, *H, *Z, *S2, *Acat, *Bcat;
    cudaGetSymbolAddress((void**)&cnt, g_cnt);
    cudaGetSymbolAddress((void**)&rowptr, g_rowptr);
    cudaGetSymbolAddress((void**)&woff, g_woff);
    cudaGetSymbolAddress((void**)&scol, g_scol);
    cudaGetSymbolAddress((void**)&sval, g_sval);
    cudaGetSymbolAddress((void**)&Y, g_Y);
    cudaGetSymbolAddress((void**)&S, g_S);
    cudaGetSymbolAddress((void**)&H, g_H);
    cudaGetSymbolAddress((void**)&Z, g_Z);
    cudaGetSymbolAddress((void**)&S2, g_S2);
    cudaGetSymbolAddress((void**)&Acat, g_Acat);
    cudaGetSymbolAddress((void**)&Bcat, g_Bcat);

    // CSR build (deterministic work per launch)
    zero_i<<<(N + 255) / 256, 256>>>(cnt, N);
    hist_k<<<(E + 255) / 256, 256>>>(rows, cnt, E);
    scan_k<<<1, 1024>>>(cnt, rowptr, woff, N, E);
    scatter_k<<<(E + 255) / 256, 256>>>(rows, cols, vals, woff, scol, sval, E);

    // weight re-layout
    prep_w<<<(256 * 768 + 256 * 192 + 255) / 256, 256>>>(W1, W2, Acat, Bcat);

    int mtiles = (N + 127) / 128;

    // Layer 1: Y = x @ [A0-A2 | A1 | A2]  ->  u0 | u1 | p
    sgemm<128, 8><<<dim3(mtiles, 6), 256>>>(x, Acat, Y, N, 768);
    // s = u1 + 2 * L p
    spmm_k<64, false, false><<<(N + 3) / 4, 256>>>(rowptr, scol, sval,
        (const float4*)Y + 128, 192, (const float4*)Y + 64, 192,
        (float4*)S, 64, nullptr, 2.0f, N);
    // h = relu(u0 + L s + b1)
    spmm_k<64, true, true><<<(N + 3) / 4, 256>>>(rowptr, scol, sval,
        (const float4*)S, 64, (const float4*)Y, 192,
        (float4*)H, 64, b1, 1.0f, N);

    // Layer 2: Z = h @ [B0-B2 | B1 | B2]  ->  v0 | v1 | p2
    sgemm<64, 4><<<dim3(mtiles, 3), 256>>>(H, Bcat, Z, N, 192);
    // s2 = v1 + 2 * L p2
    spmm_k<16, false, false><<<(N + 15) / 16, 256>>>(rowptr, scol, sval,
        (const float4*)Z + 32, 48, (const float4*)Z + 16, 48,
        (float4*)S2, 16, nullptr, 2.0f, N);
    // out = v0 + L s2 + b2
    spmm_k<16, false, true><<<(N + 15) / 16, 256>>>(rowptr, scol, sval,
        (const float4*)S2, 16, (const float4*)Z, 48,
        (float4*)outp, 16, b2, 1.0f, N);
}